// round 10
// baseline (speedup 1.0000x reference)
#include <cuda_runtime.h>

// out[b,s,f,o] = sum_{t,k,c} x[b, s+t-2, f*(k+1), c] * W[t,k,c,o],  f*(k+1) < F
// x [4,1024,512,4] f32, W [5,4,4,4] f32, out [4,1024,512,4] f32.
//
// R10: exactly R6 (c-packed FFMA2, 4-slot ring buffer, __constant__ weights,
//      64-reg cap, occ ~40%) + block-uniform interior/boundary template split:
//      126/128 s-blocks run with ZERO boundary predicates/selects on loads.

#define B_  4
#define S_  1024
#define F_  512
#define U_  4
#define NT  5
#define NK  4
#define TPB 256

typedef unsigned long long u64;

// Wc2[(k*NT+t)*4 + o] : floats (c0,c1,c2,c3) -> .x=(c0,c1) .y=(c2,c3)
__constant__ ulonglong2 Wc2[NK * NT * 4];
__device__ float Wt_scratch[NT * NK * 16];

__global__ void transpose_w_kernel(const float* __restrict__ W)
{
    int i = threadIdx.x;
    if (i < NT * NK * 16) {
        int o = i & 3, c = (i >> 2) & 3, k = (i >> 4) & 3, t = i >> 6;
        Wt_scratch[((k * NT + t) * 4 + o) * 4 + c] = W[i];
    }
}

__device__ __forceinline__ u64 fma2(u64 a, u64 b, u64 c) {
    u64 d;
    asm("fma.rn.f32x2 %0, %1, %2, %3;" : "=l"(d) : "l"(a), "l"(b), "l"(c));
    return d;
}

template <bool GUARD>
__device__ __forceinline__ void body(
    int f, int s0, const ulonglong2* __restrict__ xb, u64 acc[U_][4])
{
    for (int k = 0; k < NK; ++k) {
        int fk = f * (k + 1);
        if (fk >= F_) break;                      // monotone in k, warp-coherent
        const ulonglong2* __restrict__ col = xb + fk;

        // ring buffer: w4[m & 3] holds row m (sp = s0 + m - 2), m = 0..7
        ulonglong2 w4[4];
#pragma unroll
        for (int m = 0; m < 4; ++m) {
            int sp = s0 + m - 2;
            if (GUARD)
                w4[m] = (sp >= 0 && sp < S_) ? col[(size_t)sp * F_]
                                             : make_ulonglong2(0ull, 0ull);
            else
                w4[m] = col[(size_t)sp * F_];
        }

#pragma unroll
        for (int t = 0; t < NT; ++t) {
            ulonglong2 w0 = Wc2[(k * NT + t) * 4 + 0];
            ulonglong2 w1 = Wc2[(k * NT + t) * 4 + 1];
            ulonglong2 w2 = Wc2[(k * NT + t) * 4 + 2];
            ulonglong2 w3 = Wc2[(k * NT + t) * 4 + 3];
#pragma unroll
            for (int j = 0; j < U_; ++j) {
                ulonglong2 rv = w4[(t + j) & 3];
                acc[j][0] = fma2(rv.x, w0.x, acc[j][0]);
                acc[j][1] = fma2(rv.x, w1.x, acc[j][1]);
                acc[j][2] = fma2(rv.x, w2.x, acc[j][2]);
                acc[j][3] = fma2(rv.x, w3.x, acc[j][3]);
                acc[j][0] = fma2(rv.y, w0.y, acc[j][0]);
                acc[j][1] = fma2(rv.y, w1.y, acc[j][1]);
                acc[j][2] = fma2(rv.y, w2.y, acc[j][2]);
                acc[j][3] = fma2(rv.y, w3.y, acc[j][3]);
            }
            if (t < NT - 1) {                     // load row m = t+4 into w4[t & 3]
                int sp = s0 + t + 2;
                if (GUARD)
                    w4[t & 3] = (sp < S_) ? col[(size_t)sp * F_]
                                          : make_ulonglong2(0ull, 0ull);
                else
                    w4[t & 3] = col[(size_t)sp * F_];
            }
        }
    }
}

__global__ __launch_bounds__(TPB, 4) void harm_conv_kernel(
    const float* __restrict__ x,
    float* __restrict__ out)
{
    int gid = blockIdx.x * TPB + threadIdx.x;
    int f  = gid & (F_ - 1);                      // fastest: coalesced k=0 + stores
    int sb = (gid >> 9) & (S_ / U_ - 1);          // block-uniform
    int b  = gid >> 17;
    int s0 = sb * U_;

    const ulonglong2* __restrict__ xb =
        reinterpret_cast<const ulonglong2*>(x) + (size_t)b * S_ * F_;

    u64 acc[U_][4];                               // [j][o], packed over c-pairs
#pragma unroll
    for (int j = 0; j < U_; ++j)
#pragma unroll
        for (int o = 0; o < 4; ++o) acc[j][o] = 0ull;

    if (sb > 0 && sb < S_ / U_ - 1)               // block-uniform branch
        body<false>(f, s0, xb, acc);
    else
        body<true>(f, s0, xb, acc);

    // epilogue: fold the two c-halves per output
    float4* __restrict__ o4 =
        reinterpret_cast<float4*>(out) + ((size_t)(b * S_ + s0)) * F_ + f;
#pragma unroll
    for (int j = 0; j < U_; ++j) {
        float2 a0 = reinterpret_cast<float2&>(acc[j][0]);
        float2 a1 = reinterpret_cast<float2&>(acc[j][1]);
        float2 a2 = reinterpret_cast<float2&>(acc[j][2]);
        float2 a3 = reinterpret_cast<float2&>(acc[j][3]);
        o4[(size_t)j * F_] = make_float4(a0.x + a0.y, a1.x + a1.y,
                                         a2.x + a2.y, a3.x + a3.y);
    }
}

extern "C" void kernel_launch(void* const* d_in, const int* in_sizes, int n_in,
                              void* d_out, int out_size)
{
    const float* x = (const float*)d_in[0];
    const float* W = (const float*)d_in[1];
    float* out = (float*)d_out;

    transpose_w_kernel<<<1, NT * NK * 16>>>(W);

    void* wt_dev = nullptr;
    cudaGetSymbolAddress(&wt_dev, Wt_scratch);
    cudaMemcpyToSymbolAsync(Wc2, wt_dev, NT * NK * 16 * sizeof(float), 0,
                            cudaMemcpyDeviceToDevice, 0);

    int total = B_ * (S_ / U_) * F_;              // one thread per (b, 4s, f)
    harm_conv_kernel<<<total / TPB, TPB>>>(x, out);
}

// round 11
// speedup vs baseline: 1.4444x; 1.4444x over previous
#include <cuda_runtime.h>

// out[b,s,f,o] = sum_{t,k,c} x[b, s+t-2, f*(k+1), c] * W[t,k,c,o],  f*(k+1) < F
// x [4,1024,512,4] f32, W [5,4,4,4] f32, out [4,1024,512,4] f32.
//
// R11: smem-staged rows. Block = 512 threads = full F for one (b, 4s) slab.
//      8 rows (64KB) staged coalesced -> all harmonic gathers become fixed-
//      latency LDS (no L2 scoreboard stalls). Uniform blocks. FFMA2 c-packed,
//      __constant__ weights, LDS-fed ring buffer, ~60 regs, 2 blocks/SM.

#define B_  4
#define S_  1024
#define F_  512
#define U_  4
#define NT  5
#define NK  4
#define TPB 512

typedef unsigned long long u64;

__constant__ ulonglong2 Wc2[NK * NT * 4];   // [(k*NT+t)*4+o] c-pairs
__device__ float Wt_scratch[NT * NK * 16];

__global__ void transpose_w_kernel(const float* __restrict__ W)
{
    int i = threadIdx.x;
    if (i < NT * NK * 16) {
        int o = i & 3, c = (i >> 2) & 3, k = (i >> 4) & 3, t = i >> 6;
        Wt_scratch[((k * NT + t) * 4 + o) * 4 + c] = W[i];
    }
}

__device__ __forceinline__ u64 fma2(u64 a, u64 b, u64 c) {
    u64 d;
    asm("fma.rn.f32x2 %0, %1, %2, %3;" : "=l"(d) : "l"(a), "l"(b), "l"(c));
    return d;
}

__global__ __launch_bounds__(TPB, 2) void harm_conv_kernel(
    const float* __restrict__ x,
    float* __restrict__ out)
{
    extern __shared__ ulonglong2 tile[];        // [8][F_] rows s0-2 .. s0+5

    int bx = blockIdx.x;
    int sb = bx & (S_ / U_ - 1);
    int b  = bx >> 8;                            // S_/U_ = 256 blocks per b
    int s0 = sb * U_;
    int f  = threadIdx.x;

    const ulonglong2* __restrict__ xb =
        reinterpret_cast<const ulonglong2*>(x) + (size_t)b * S_ * F_;

    // ── stage 8 full rows, coalesced, MLP=8 ──
    if (sb > 0 && sb < S_ / U_ - 1) {
        const ulonglong2* __restrict__ src = xb + (size_t)(s0 - 2) * F_ + f;
#pragma unroll
        for (int i = 0; i < U_ + 4; ++i)
            tile[i * F_ + f] = src[(size_t)i * F_];
    } else {
#pragma unroll
        for (int i = 0; i < U_ + 4; ++i) {
            int sp = s0 + i - 2;
            tile[i * F_ + f] = (sp >= 0 && sp < S_)
                             ? xb[(size_t)sp * F_ + f]
                             : make_ulonglong2(0ull, 0ull);
        }
    }
    __syncthreads();

    u64 acc[U_][4];                              // [j][o], packed over c-pairs
#pragma unroll
    for (int j = 0; j < U_; ++j)
#pragma unroll
        for (int o = 0; o < 4; ++o) acc[j][o] = 0ull;

    for (int k = 0; k < NK; ++k) {
        int fk = f * (k + 1);
        if (fk >= F_) break;                     // monotone in k, warp-coherent
        const ulonglong2* __restrict__ col = tile + fk;

        // ring: w4[m & 3] holds row m (smem row index m), m = 0..7
        ulonglong2 w4[4];
#pragma unroll
        for (int m = 0; m < 4; ++m)
            w4[m] = col[m * F_];

#pragma unroll
        for (int t = 0; t < NT; ++t) {
            ulonglong2 w0 = Wc2[(k * NT + t) * 4 + 0];
            ulonglong2 w1 = Wc2[(k * NT + t) * 4 + 1];
            ulonglong2 w2 = Wc2[(k * NT + t) * 4 + 2];
            ulonglong2 w3 = Wc2[(k * NT + t) * 4 + 3];
#pragma unroll
            for (int j = 0; j < U_; ++j) {
                ulonglong2 rv = w4[(t + j) & 3];
                acc[j][0] = fma2(rv.x, w0.x, acc[j][0]);
                acc[j][1] = fma2(rv.x, w1.x, acc[j][1]);
                acc[j][2] = fma2(rv.x, w2.x, acc[j][2]);
                acc[j][3] = fma2(rv.x, w3.x, acc[j][3]);
                acc[j][0] = fma2(rv.y, w0.y, acc[j][0]);
                acc[j][1] = fma2(rv.y, w1.y, acc[j][1]);
                acc[j][2] = fma2(rv.y, w2.y, acc[j][2]);
                acc[j][3] = fma2(rv.y, w3.y, acc[j][3]);
            }
            if (t < NT - 1)                      // load row t+4 into slot t&3
                w4[t & 3] = col[(t + 4) * F_];
        }
    }

    // epilogue: fold the two c-halves per output
    float4* __restrict__ o4 =
        reinterpret_cast<float4*>(out) + ((size_t)(b * S_ + s0)) * F_ + f;
#pragma unroll
    for (int j = 0; j < U_; ++j) {
        float2 a0 = reinterpret_cast<float2&>(acc[j][0]);
        float2 a1 = reinterpret_cast<float2&>(acc[j][1]);
        float2 a2 = reinterpret_cast<float2&>(acc[j][2]);
        float2 a3 = reinterpret_cast<float2&>(acc[j][3]);
        o4[(size_t)j * F_] = make_float4(a0.x + a0.y, a1.x + a1.y,
                                         a2.x + a2.y, a3.x + a3.y);
    }
}

extern "C" void kernel_launch(void* const* d_in, const int* in_sizes, int n_in,
                              void* d_out, int out_size)
{
    const float* x = (const float*)d_in[0];
    const float* W = (const float*)d_in[1];
    float* out = (float*)d_out;

    const int SMEM = (U_ + 4) * F_ * 16;         // 64 KB

    // set once on the (non-captured) correctness call; ignore error if the
    // call happens under capture — the attribute is already sticky.
    (void)cudaFuncSetAttribute(harm_conv_kernel,
                               cudaFuncAttributeMaxDynamicSharedMemorySize,
                               SMEM);

    transpose_w_kernel<<<1, NT * NK * 16>>>(W);

    void* wt_dev = nullptr;
    cudaGetSymbolAddress(&wt_dev, Wt_scratch);
    cudaMemcpyToSymbolAsync(Wc2, wt_dev, NT * NK * 16 * sizeof(float), 0,
                            cudaMemcpyDeviceToDevice, 0);

    int blocks = B_ * (S_ / U_);                 // 1024 uniform blocks
    harm_conv_kernel<<<blocks, TPB, SMEM>>>(x, out);
}

// round 12
// speedup vs baseline: 1.4752x; 1.0213x over previous
#include <cuda_runtime.h>

// out[b,s,f,o] = sum_{t,k,c} x[b, s+t-2, f*(k+1), c] * W[t,k,c,o],  f*(k+1) < F
// x [4,1024,512,4] f32, W [5,4,4,4] f32, out [4,1024,512,4] f32.
//
// R12: R11 (smem-staged full-F rows, LDS gathers, FFMA2 c-packed, __constant__
//      weights) + intra-block warp balancing: 256-thread blocks, each warp
//      owns heavy chunk w (full k loop) AND light chunk w+8 (f>=256, k=0 only)
//      -> warp costs {5,5,5,5,4,4,3,3} vs R11's {20..5}, 3 blocks/SM.

#define B_  4
#define S_  1024
#define F_  512
#define U_  4
#define NT  5
#define NK  4
#define TPB 256

typedef unsigned long long u64;

__constant__ ulonglong2 Wc2[NK * NT * 4];   // [(k*NT+t)*4+o] c-pairs
__device__ float Wt_scratch[NT * NK * 16];

__global__ void transpose_w_kernel(const float* __restrict__ W)
{
    int i = threadIdx.x;
    if (i < NT * NK * 16) {
        int o = i & 3, c = (i >> 2) & 3, k = (i >> 4) & 3, t = i >> 6;
        Wt_scratch[((k * NT + t) * 4 + o) * 4 + c] = W[i];
    }
}

__device__ __forceinline__ u64 fma2(u64 a, u64 b, u64 c) {
    u64 d;
    asm("fma.rn.f32x2 %0, %1, %2, %3;" : "=l"(d) : "l"(a), "l"(b), "l"(c));
    return d;
}

// one harmonic k: 5 taps x 4 outputs over ring-buffered rows of `col`
__device__ __forceinline__ void harmonic(
    const ulonglong2* __restrict__ col, int k, u64 acc[U_][4])
{
    ulonglong2 w4[4];
#pragma unroll
    for (int m = 0; m < 4; ++m) w4[m] = col[m * F_];

#pragma unroll
    for (int t = 0; t < NT; ++t) {
        ulonglong2 w0 = Wc2[(k * NT + t) * 4 + 0];
        ulonglong2 w1 = Wc2[(k * NT + t) * 4 + 1];
        ulonglong2 w2 = Wc2[(k * NT + t) * 4 + 2];
        ulonglong2 w3 = Wc2[(k * NT + t) * 4 + 3];
#pragma unroll
        for (int j = 0; j < U_; ++j) {
            ulonglong2 rv = w4[(t + j) & 3];
            acc[j][0] = fma2(rv.x, w0.x, acc[j][0]);
            acc[j][1] = fma2(rv.x, w1.x, acc[j][1]);
            acc[j][2] = fma2(rv.x, w2.x, acc[j][2]);
            acc[j][3] = fma2(rv.x, w3.x, acc[j][3]);
            acc[j][0] = fma2(rv.y, w0.y, acc[j][0]);
            acc[j][1] = fma2(rv.y, w1.y, acc[j][1]);
            acc[j][2] = fma2(rv.y, w2.y, acc[j][2]);
            acc[j][3] = fma2(rv.y, w3.y, acc[j][3]);
        }
        if (t < NT - 1) w4[t & 3] = col[(t + 4) * F_];
    }
}

__device__ __forceinline__ void store4(
    float4* __restrict__ o4, const u64 acc[U_][4])
{
#pragma unroll
    for (int j = 0; j < U_; ++j) {
        float2 a0 = reinterpret_cast<const float2&>(acc[j][0]);
        float2 a1 = reinterpret_cast<const float2&>(acc[j][1]);
        float2 a2 = reinterpret_cast<const float2&>(acc[j][2]);
        float2 a3 = reinterpret_cast<const float2&>(acc[j][3]);
        o4[(size_t)j * F_] = make_float4(a0.x + a0.y, a1.x + a1.y,
                                         a2.x + a2.y, a3.x + a3.y);
    }
}

__global__ __launch_bounds__(TPB, 3) void harm_conv_kernel(
    const float* __restrict__ x,
    float* __restrict__ out)
{
    extern __shared__ ulonglong2 tile[];          // [8][F_] rows s0-2 .. s0+5

    int bx = blockIdx.x;
    int sb = bx & (S_ / U_ - 1);
    int b  = bx >> 8;
    int s0 = sb * U_;
    int tid = threadIdx.x;

    const ulonglong2* __restrict__ xb =
        reinterpret_cast<const ulonglong2*>(x) + (size_t)b * S_ * F_;

    // ── stage 8 full rows (each thread: 2 cols x 8 rows), coalesced ──
    if (sb > 0 && sb < S_ / U_ - 1) {
        const ulonglong2* __restrict__ src = xb + (size_t)(s0 - 2) * F_ + tid;
#pragma unroll
        for (int i = 0; i < U_ + 4; ++i) {
            tile[i * F_ + tid]       = src[(size_t)i * F_];
            tile[i * F_ + tid + TPB] = src[(size_t)i * F_ + TPB];
        }
    } else {
#pragma unroll
        for (int i = 0; i < U_ + 4; ++i) {
            int sp = s0 + i - 2;
            if (sp >= 0 && sp < S_) {
                tile[i * F_ + tid]       = xb[(size_t)sp * F_ + tid];
                tile[i * F_ + tid + TPB] = xb[(size_t)sp * F_ + tid + TPB];
            } else {
                tile[i * F_ + tid]       = make_ulonglong2(0ull, 0ull);
                tile[i * F_ + tid + TPB] = make_ulonglong2(0ull, 0ull);
            }
        }
    }
    __syncthreads();

    float4* __restrict__ obase =
        reinterpret_cast<float4*>(out) + ((size_t)(b * S_ + s0)) * F_;

    // ── heavy chunk: f1 = tid (f < 256), full harmonic loop ──
    int f1 = tid;
    {
        u64 acc[U_][4];
#pragma unroll
        for (int j = 0; j < U_; ++j)
#pragma unroll
            for (int o = 0; o < 4; ++o) acc[j][o] = 0ull;

        for (int k = 0; k < NK; ++k) {
            int fk = f1 * (k + 1);
            if (fk >= F_) break;                  // near-coherent; predicated
            harmonic(tile + fk, k, acc);
        }
        store4(obase + f1, acc);
    }

    // ── light chunk: f2 = tid + 256 (f >= 256), k = 0 only ──
    int f2 = tid + TPB;
    {
        u64 acc[U_][4];
#pragma unroll
        for (int j = 0; j < U_; ++j)
#pragma unroll
            for (int o = 0; o < 4; ++o) acc[j][o] = 0ull;

        harmonic(tile + f2, 0, acc);
        store4(obase + f2, acc);
    }
}

extern "C" void kernel_launch(void* const* d_in, const int* in_sizes, int n_in,
                              void* d_out, int out_size)
{
    const float* x = (const float*)d_in[0];
    const float* W = (const float*)d_in[1];
    float* out = (float*)d_out;

    const int SMEM = (U_ + 4) * F_ * 16;          // 64 KB

    (void)cudaFuncSetAttribute(harm_conv_kernel,
                               cudaFuncAttributeMaxDynamicSharedMemorySize,
                               SMEM);

    transpose_w_kernel<<<1, NT * NK * 16>>>(W);

    void* wt_dev = nullptr;
    cudaGetSymbolAddress(&wt_dev, Wt_scratch);
    cudaMemcpyToSymbolAsync(Wc2, wt_dev, NT * NK * 16 * sizeof(float), 0,
                            cudaMemcpyDeviceToDevice, 0);

    int blocks = B_ * (S_ / U_);                  // 1024 uniform blocks
    harm_conv_kernel<<<blocks, TPB, SMEM>>>(x, out);
}

// round 13
// speedup vs baseline: 1.5878x; 1.0763x over previous
#include <cuda_runtime.h>

// out[b,s,f,o] = sum_{t,k,c} x[b, s+t-2, f*(k+1), c] * W[t,k,c,o],  f*(k+1) < F
// x [4,1024,512,4] f32, W [5,4,4,4] f32, out [4,1024,512,4] f32.
//
// R13: R12 (smem-staged full-F rows, LDS gathers, warp balancing) with FFMA2
//      packing switched c-pairs -> o-pairs: raw W layout is directly usable as
//      packed constants (NO transpose kernel node; one memcpy node remains),
//      and the horizontal-add epilogue disappears (acc pairs = output layout).

#define B_  4
#define S_  1024
#define F_  512
#define U_  4
#define NT  5
#define NK  4
#define TPB 256

typedef unsigned long long u64;

// raw layout: WcR[t][k][c] = (W[t][k][c][0..1], W[t][k][c][2..3]) as o-pairs
__constant__ ulonglong2 WcR[NT][NK][4];

__device__ __forceinline__ u64 fma2(u64 a, u64 b, u64 c) {
    u64 d;
    asm("fma.rn.f32x2 %0, %1, %2, %3;" : "=l"(d) : "l"(a), "l"(b), "l"(c));
    return d;
}
__device__ __forceinline__ u64 dup2(float v) {
    u64 d;
    asm("mov.b64 %0, {%1, %1};" : "=l"(d) : "f"(v));
    return d;
}

struct Row { u64 c0, c1, c2, c3; };              // dup'd channel values

__device__ __forceinline__ Row loadRow(const float4* __restrict__ p) {
    float4 v = *p;
    Row r;
    r.c0 = dup2(v.x); r.c1 = dup2(v.y); r.c2 = dup2(v.z); r.c3 = dup2(v.w);
    return r;
}

// one harmonic k: 5 taps x 4 outputs over ring-buffered rows of `col`
__device__ __forceinline__ void harmonic(
    const float4* __restrict__ col, int k, u64 acc[U_][2])
{
    Row w4[4];
#pragma unroll
    for (int m = 0; m < 4; ++m) w4[m] = loadRow(col + m * F_);

#pragma unroll
    for (int t = 0; t < NT; ++t) {
        ulonglong2 q0 = WcR[t][k][0];
        ulonglong2 q1 = WcR[t][k][1];
        ulonglong2 q2 = WcR[t][k][2];
        ulonglong2 q3 = WcR[t][k][3];
#pragma unroll
        for (int j = 0; j < U_; ++j) {
            Row rv = w4[(t + j) & 3];
            acc[j][0] = fma2(rv.c0, q0.x, acc[j][0]);
            acc[j][1] = fma2(rv.c0, q0.y, acc[j][1]);
            acc[j][0] = fma2(rv.c1, q1.x, acc[j][0]);
            acc[j][1] = fma2(rv.c1, q1.y, acc[j][1]);
            acc[j][0] = fma2(rv.c2, q2.x, acc[j][0]);
            acc[j][1] = fma2(rv.c2, q2.y, acc[j][1]);
            acc[j][0] = fma2(rv.c3, q3.x, acc[j][0]);
            acc[j][1] = fma2(rv.c3, q3.y, acc[j][1]);
        }
        if (t < NT - 1) w4[t & 3] = loadRow(col + (t + 4) * F_);
    }
}

__device__ __forceinline__ void store4(
    float4* __restrict__ o4, const u64 acc[U_][2])
{
#pragma unroll
    for (int j = 0; j < U_; ++j) {
        float2 lo = reinterpret_cast<const float2&>(acc[j][0]);
        float2 hi = reinterpret_cast<const float2&>(acc[j][1]);
        o4[(size_t)j * F_] = make_float4(lo.x, lo.y, hi.x, hi.y);
    }
}

__global__ __launch_bounds__(TPB, 3) void harm_conv_kernel(
    const float* __restrict__ x,
    float* __restrict__ out)
{
    extern __shared__ float4 tile[];              // [8][F_] rows s0-2 .. s0+5

    int bx = blockIdx.x;
    int sb = bx & (S_ / U_ - 1);
    int b  = bx >> 8;
    int s0 = sb * U_;
    int tid = threadIdx.x;

    const float4* __restrict__ xb =
        reinterpret_cast<const float4*>(x) + (size_t)b * S_ * F_;

    // ── stage 8 full rows (each thread: 2 cols x 8 rows), coalesced ──
    if (sb > 0 && sb < S_ / U_ - 1) {
        const float4* __restrict__ src = xb + (size_t)(s0 - 2) * F_ + tid;
#pragma unroll
        for (int i = 0; i < U_ + 4; ++i) {
            tile[i * F_ + tid]       = src[(size_t)i * F_];
            tile[i * F_ + tid + TPB] = src[(size_t)i * F_ + TPB];
        }
    } else {
#pragma unroll
        for (int i = 0; i < U_ + 4; ++i) {
            int sp = s0 + i - 2;
            if (sp >= 0 && sp < S_) {
                tile[i * F_ + tid]       = xb[(size_t)sp * F_ + tid];
                tile[i * F_ + tid + TPB] = xb[(size_t)sp * F_ + tid + TPB];
            } else {
                tile[i * F_ + tid]       = make_float4(0.f, 0.f, 0.f, 0.f);
                tile[i * F_ + tid + TPB] = make_float4(0.f, 0.f, 0.f, 0.f);
            }
        }
    }
    __syncthreads();

    float4* __restrict__ obase =
        reinterpret_cast<float4*>(out) + ((size_t)(b * S_ + s0)) * F_;

    // ── heavy chunk: f1 = tid (f < 256), full harmonic loop ──
    int f1 = tid;
    {
        u64 acc[U_][2];
#pragma unroll
        for (int j = 0; j < U_; ++j) { acc[j][0] = 0ull; acc[j][1] = 0ull; }

        for (int k = 0; k < NK; ++k) {
            int fk = f1 * (k + 1);
            if (fk >= F_) break;                  // near-coherent within warp
            harmonic(tile + fk, k, acc);
        }
        store4(obase + f1, acc);
    }

    // ── light chunk: f2 = tid + 256 (f >= 256), k = 0 only ──
    int f2 = tid + TPB;
    {
        u64 acc[U_][2];
#pragma unroll
        for (int j = 0; j < U_; ++j) { acc[j][0] = 0ull; acc[j][1] = 0ull; }

        harmonic(tile + f2, 0, acc);
        store4(obase + f2, acc);
    }
}

extern "C" void kernel_launch(void* const* d_in, const int* in_sizes, int n_in,
                              void* d_out, int out_size)
{
    const float* x = (const float*)d_in[0];
    const float* W = (const float*)d_in[1];
    float* out = (float*)d_out;

    const int SMEM = (U_ + 4) * F_ * 16;          // 64 KB

    (void)cudaFuncSetAttribute(harm_conv_kernel,
                               cudaFuncAttributeMaxDynamicSharedMemorySize,
                               SMEM);

    // raw W layout IS the o-pair packed layout: direct copy, no transpose node
    cudaMemcpyToSymbolAsync(WcR, W, NT * NK * 16 * sizeof(float), 0,
                            cudaMemcpyDeviceToDevice, 0);

    int blocks = B_ * (S_ / U_);                  // 1024 uniform blocks
    harm_conv_kernel<<<blocks, TPB, SMEM>>>(x, out);
}